// round 14
// baseline (speedup 1.0000x reference)
#include <cuda_runtime.h>
#include <cuda_bf16.h>
#include <math.h>
#include <stdint.h>

#define H 1024
#define B 256
#define T 256
#define C 10

#define M_TILE 64
#define N_TILE 64
#define KC 64
#define NCHUNK 16
#define N_THREADS 128
#define NSTAGE 3

#define ROW_BYTES 144
#define A_PLANE_BYTES (M_TILE * ROW_BYTES)      // 9216
#define B_PLANE_BYTES (N_TILE * ROW_BYTES)      // 9216
#define OFF_AH 0
#define OFF_AL A_PLANE_BYTES
#define OFF_BH (2 * A_PLANE_BYTES)
#define OFF_BL (2 * A_PLANE_BYTES + B_PLANE_BYTES)
#define STAGE_BYTES (2 * A_PLANE_BYTES + 2 * B_PLANE_BYTES)   // 36864
#define SMEM_TOTAL (NSTAGE * STAGE_BYTES)                     // 110592 -> 2 CTA/SM
#define EP_STRIDE 65

// ---- persistent device state (no allocation) ----
__device__ __nv_bfloat16 g_pw[2][4096][1024];   // packed W planes [hi/lo][m][k]
__device__ float         g_pwx[4096];           // packed x-weights (same row perm)
__device__ float         g_xT[T * B];           // x transposed [t][b]
__device__ __nv_bfloat16 g_hbf[2][2][B][H];     // [pingpong][plane][b][i]
__device__ float         g_c[B * H];            // cell state [b][i]
__device__ float         g_h32[B * H];          // fp32 h_T for projection [b][i]

// ---------------- helpers ----------------
__device__ __forceinline__ uint32_t smem_u32(const void* p) {
    uint32_t a;
    asm("{ .reg .u64 t; cvta.to.shared.u64 t, %1; cvt.u32.u64 %0, t; }" : "=r"(a) : "l"(p));
    return a;
}
#define CP_ASYNC16(dst, src) asm volatile("cp.async.cg.shared.global [%0], [%1], 16;" :: "r"(dst), "l"(src) : "memory")
#define CP_COMMIT() asm volatile("cp.async.commit_group;" ::: "memory")
#define CP_WAIT(n)  asm volatile("cp.async.wait_group %0;" :: "n"(n) : "memory")

__device__ __forceinline__ void ldsm_x4(uint32_t* r, uint32_t addr) {
    asm volatile("ldmatrix.sync.aligned.m8n8.x4.shared.b16 {%0,%1,%2,%3}, [%4];"
        : "=r"(r[0]), "=r"(r[1]), "=r"(r[2]), "=r"(r[3]) : "r"(addr));
}
__device__ __forceinline__ void mma_bf16(float* d, const uint32_t* a,
                                         uint32_t b0, uint32_t b1) {
    asm volatile("mma.sync.aligned.m16n8k16.row.col.f32.bf16.bf16.f32 "
        "{%0,%1,%2,%3}, {%4,%5,%6,%7}, {%8,%9}, {%0,%1,%2,%3};"
        : "+f"(d[0]), "+f"(d[1]), "+f"(d[2]), "+f"(d[3])
        : "r"(a[0]), "r"(a[1]), "r"(a[2]), "r"(a[3]), "r"(b0), "r"(b1));
}
__device__ __forceinline__ float sigm(float v) { return 1.0f / (1.0f + __expf(-v)); }
__device__ __forceinline__ float tanh_fast(float v) { return 2.0f * sigm(2.0f * v) - 1.0f; }

// ---------------- pack / init ----------------
// Row permutation: m = ((i>>4) << 6) | (gate << 4) | (i & 15)
__global__ void pack_w_kernel(const float* __restrict__ Wgh, const float* __restrict__ Wih,
                              const float* __restrict__ Wfh, const float* __restrict__ Woh) {
    int idx = blockIdx.x * 256 + threadIdx.x;           // 4M
    int gate = idx >> 20;
    int rem = idx & 0xFFFFF;
    int i = rem >> 10;
    int k = rem & 1023;
    const float* W = (gate == 0) ? Wgh : (gate == 1) ? Wih : (gate == 2) ? Wfh : Woh;
    float w = W[i * H + k];
    __nv_bfloat16 hi = __float2bfloat16(w);
    float lo = w - __bfloat162float(hi);
    int m = ((i >> 4) << 6) + (gate << 4) + (i & 15);
    g_pw[0][m][k] = hi;
    g_pw[1][m][k] = __float2bfloat16(lo);
}

__global__ void pack_wx_kernel(const float* __restrict__ Wgx, const float* __restrict__ Wix,
                               const float* __restrict__ Wfx, const float* __restrict__ Wox,
                               const float* __restrict__ x) {
    int idx = blockIdx.x * 256 + threadIdx.x;
    if (idx < 4096) {
        int gate = idx >> 10;
        int i = idx & 1023;
        const float* W = (gate == 0) ? Wgx : (gate == 1) ? Wix : (gate == 2) ? Wfx : Wox;
        int m = ((i >> 4) << 6) + (gate << 4) + (i & 15);
        g_pwx[m] = W[i];
    }
    if (idx < T * B) {
        int tt = idx >> 8;
        int bb = idx & 255;
        g_xT[tt * B + bb] = x[bb * T + tt];
    }
}

__global__ void lstm_init_kernel() {
    int idx = blockIdx.x * 256 + threadIdx.x;           // 524288
    if (idx < 262144) {
        ((uint32_t*)&g_hbf[0][0][0][0])[idx] = 0;       // zero pp0 hi+lo planes
    } else {
        g_c[idx - 262144] = 0.0f;
    }
}

// ---------------- one timestep ----------------
// grid (64, 4): mt = 64-row block of packed W (4 gates x 16 h-rows), nt = 64-batch block.
// 4 warps, warp tile 32x32 (2x2 warp grid) -> minimal fragment redundancy.
__global__ void __launch_bounds__(N_THREADS, 2) lstm_step_kernel(
    const float* __restrict__ bg, const float* __restrict__ bi,
    const float* __restrict__ bf, const float* __restrict__ bo,
    int t)
{
    extern __shared__ char smem[];
    const uint32_t sb = smem_u32(smem);
    const int tid = threadIdx.x;
    const int lane = tid & 31;
    const int wid = tid >> 5;
    const int warp_m = wid & 1;          // 2 m-warps x 32 rows
    const int warp_n = wid >> 1;         // 2 n-warps x 32 cols
    const int mt = blockIdx.x;
    const int nt = blockIdx.y;
    const int pp = t & 1;
    const int ppo = pp ^ 1;

    const __nv_bfloat16* srcAh = &g_pw[0][mt * M_TILE][0];
    const __nv_bfloat16* srcAl = &g_pw[1][mt * M_TILE][0];

    // per-thread cp.async decode: A and B each 8 x 16B chunks per thread (128 thr)
    const __nv_bfloat16* aSrc[8];
    uint32_t aDst[8];
    const __nv_bfloat16* bSrc[8];
    uint32_t bDst[8];
#pragma unroll
    for (int it = 0; it < 8; it++) {
        int i = tid + it * 128;
        int c8 = i & 7, row = (i >> 3) & 63, pl = i >> 9;
        aSrc[it] = (pl ? srcAl : srcAh) + row * H + c8 * 8;
        aDst[it] = (pl ? OFF_AL : OFF_AH) + row * ROW_BYTES + c8 * 16;
        bSrc[it] = &g_hbf[pp][pl][nt * N_TILE + row][0] + c8 * 8;
        bDst[it] = (pl ? OFF_BL : OFF_BH) + row * ROW_BYTES + c8 * 16;
    }

    const uint32_t lm_a = (uint32_t)((warp_m * 32 + (lane & 15)) * ROW_BYTES + (lane >> 4) * 16);
    const uint32_t lm_b = (uint32_t)((warp_n * 32 + (lane & 15)) * ROW_BYTES + (lane >> 4) * 16);

    float d[2][4][4];    // [m2][n8][4] : warp 32x32 accumulators
#pragma unroll
    for (int a = 0; a < 2; a++)
#pragma unroll
        for (int b2 = 0; b2 < 4; b2++)
#pragma unroll
            for (int e = 0; e < 4; e++)
                d[a][b2][e] = 0.0f;

    // ---- prefetch chunks 0, 1 ----
#pragma unroll
    for (int cc = 0; cc < 2; cc++) {
        const uint32_t stg = sb + cc * STAGE_BYTES;
        const int k0 = cc * KC;
#pragma unroll
        for (int it = 0; it < 8; it++) {
            CP_ASYNC16(stg + aDst[it], aSrc[it] + k0);
            CP_ASYNC16(stg + bDst[it], bSrc[it] + k0);
        }
        CP_COMMIT();
    }

    // ---- main chunk loop: 1 sync per chunk, 3-stage smem pipeline ----
    for (int c = 0; c < NCHUNK; c++) {
        if (c < NCHUNK - 1) CP_WAIT(1);
        else                CP_WAIT(0);
        __syncthreads();

        if (c + 2 < NCHUNK) {
            const uint32_t stg = sb + ((c + 2) % 3) * STAGE_BYTES;
            const int k0 = (c + 2) * KC;
#pragma unroll
            for (int it = 0; it < 8; it++) {
                CP_ASYNC16(stg + aDst[it], aSrc[it] + k0);
                CP_ASYNC16(stg + bDst[it], bSrc[it] + k0);
            }
            CP_COMMIT();
        }

        const uint32_t stg = sb + (c % 3) * STAGE_BYTES;
        const uint32_t aBaseH = stg + OFF_AH + lm_a;
        const uint32_t aBaseL = stg + OFF_AL + lm_a;
        const uint32_t bBaseH = stg + OFF_BH + lm_b;
        const uint32_t bBaseL = stg + OFF_BL + lm_b;

#pragma unroll
        for (int k16 = 0; k16 < 4; k16++) {
            const uint32_t koff = (uint32_t)(k16 * 32);
            uint32_t af[2][2][4];    // [plane][m2]
            uint32_t bfr[2][2][4];   // [plane][n16-half]
            ldsm_x4(af[0][0], aBaseH + koff);
            ldsm_x4(af[0][1], aBaseH + koff + 16 * ROW_BYTES);
            ldsm_x4(af[1][0], aBaseL + koff);
            ldsm_x4(af[1][1], aBaseL + koff + 16 * ROW_BYTES);
            ldsm_x4(bfr[0][0], bBaseH + koff);
            ldsm_x4(bfr[0][1], bBaseH + koff + 16 * ROW_BYTES);
            ldsm_x4(bfr[1][0], bBaseL + koff);
            ldsm_x4(bfr[1][1], bBaseL + koff + 16 * ROW_BYTES);
#pragma unroll
            for (int combo = 0; combo < 3; combo++) {
                const int pa = (combo == 2) ? 1 : 0;
                const int pb = (combo == 1) ? 1 : 0;
#pragma unroll
                for (int m2 = 0; m2 < 2; m2++) {
                    mma_bf16(d[m2][0], af[pa][m2], bfr[pb][0][0], bfr[pb][0][2]);
                    mma_bf16(d[m2][1], af[pa][m2], bfr[pb][0][1], bfr[pb][0][3]);
                    mma_bf16(d[m2][2], af[pa][m2], bfr[pb][1][0], bfr[pb][1][2]);
                    mma_bf16(d[m2][3], af[pa][m2], bfr[pb][1][1], bfr[pb][1][3]);
                }
            }
        }
    }
    __syncthreads();   // all reads of stage smem done before ep overwrite

    // ---- accumulators -> smem exchange [64][EP_STRIDE] ----
    float* ep = (float*)smem;
#pragma unroll
    for (int m2 = 0; m2 < 2; m2++) {
        const int mrow = warp_m * 32 + m2 * 16 + (lane >> 2);
#pragma unroll
        for (int n8 = 0; n8 < 4; n8++) {
            const int ncol = warp_n * 32 + n8 * 8 + (lane & 3) * 2;
            ep[mrow * EP_STRIDE + ncol]           = d[m2][n8][0];
            ep[mrow * EP_STRIDE + ncol + 1]       = d[m2][n8][1];
            ep[(mrow + 8) * EP_STRIDE + ncol]     = d[m2][n8][2];
            ep[(mrow + 8) * EP_STRIDE + ncol + 1] = d[m2][n8][3];
        }
    }
    __syncthreads();

    // ---- pointwise LSTM update (128 threads: 16 i-rows x 8 b-col groups) ----
    const int il = tid & 15;
    const int bq = tid >> 4;             // 0..7
    const int ig = mt * 16 + il;
    const float wxg = g_pwx[mt * 64 + 0 * 16 + il];
    const float wxi = g_pwx[mt * 64 + 1 * 16 + il];
    const float wxf = g_pwx[mt * 64 + 2 * 16 + il];
    const float wxo = g_pwx[mt * 64 + 3 * 16 + il];
#pragma unroll
    for (int jj = 0; jj < 8; jj++) {
        const int bl = bq + 8 * jj;
        const int bglob = nt * N_TILE + bl;
        const float xv = g_xT[t * B + bglob];
        const float pg = ep[(0 * 16 + il) * EP_STRIDE + bl] + wxg * xv + bg[bglob];
        const float pi = ep[(1 * 16 + il) * EP_STRIDE + bl] + wxi * xv + bi[bglob];
        const float pf = ep[(2 * 16 + il) * EP_STRIDE + bl] + wxf * xv + bf[bglob];
        const float po = ep[(3 * 16 + il) * EP_STRIDE + bl] + wxo * xv + bo[bglob];

        const float gg = tanh_fast(pg);
        const float ii = sigm(pi);
        const float ff = sigm(pf);
        const float oo = sigm(po);

        const int idx = bglob * H + ig;
        const float cn = gg * ii + g_c[idx] * ff;
        g_c[idx] = cn;
        const float hn = tanh_fast(cn) * oo;
        const __nv_bfloat16 hhi = __float2bfloat16(hn);
        const float hlo = hn - __bfloat162float(hhi);
        g_hbf[ppo][0][bglob][ig] = hhi;
        g_hbf[ppo][1][bglob][ig] = __float2bfloat16(hlo);
        if (t == T - 1) g_h32[idx] = hn;
    }
}

// ---------------- projection + softmax ----------------
__global__ void __launch_bounds__(256) proj_softmax_kernel(
    const float* __restrict__ Wph, const float* __restrict__ bp,
    float* __restrict__ out)
{
    const float* __restrict__ hT = g_h32;   // [b][i]
    const int b = threadIdx.x;

    float p[C];
#pragma unroll
    for (int c = 0; c < C; c++) p[c] = 0.0f;
    for (int k = 0; k < H; k++) {
        float hv = hT[b * H + k];
#pragma unroll
        for (int c = 0; c < C; c++)
            p[c] = fmaf(Wph[c * H + k], hv, p[c]);
    }
    float bpb = bp[b];
#pragma unroll
    for (int c = 0; c < C; c++) p[c] += bpb;

    __shared__ float red[256];
    for (int c = 0; c < C; c++) {
        red[b] = p[c];
        __syncthreads();
        for (int s = 128; s > 0; s >>= 1) {
            if (b < s) red[b] = fmaxf(red[b], red[b + s]);
            __syncthreads();
        }
        float m = red[0];
        __syncthreads();
        float e = expf(p[c] - m);
        red[b] = e;
        __syncthreads();
        for (int s = 128; s > 0; s >>= 1) {
            if (b < s) red[b] += red[b + s];
            __syncthreads();
        }
        float ssum = red[0];
        __syncthreads();
        out[b * C + c] = e / ssum;
    }
}

extern "C" void kernel_launch(void* const* d_in, const int* in_sizes, int n_in,
                              void* d_out, int out_size) {
    const float* x   = (const float*)d_in[0];
    const float* Wgx = (const float*)d_in[1];
    const float* Wgh = (const float*)d_in[2];
    const float* Wix = (const float*)d_in[3];
    const float* Wih = (const float*)d_in[4];
    const float* Wfx = (const float*)d_in[5];
    const float* Wfh = (const float*)d_in[6];
    const float* Wox = (const float*)d_in[7];
    const float* Woh = (const float*)d_in[8];
    const float* Wph = (const float*)d_in[9];
    const float* bg  = (const float*)d_in[10];
    const float* bi  = (const float*)d_in[11];
    const float* bfv = (const float*)d_in[12];
    const float* bo  = (const float*)d_in[13];
    const float* bp  = (const float*)d_in[14];
    float* out = (float*)d_out;

    cudaFuncSetAttribute(lstm_step_kernel,
                         cudaFuncAttributeMaxDynamicSharedMemorySize, SMEM_TOTAL);

    pack_w_kernel<<<4 * 1024 * 1024 / 256, 256>>>(Wgh, Wih, Wfh, Woh);
    pack_wx_kernel<<<(T * B + 255) / 256, 256>>>(Wgx, Wix, Wfx, Wox, x);
    lstm_init_kernel<<<524288 / 256, 256>>>();

    dim3 grid(4096 / M_TILE, B / N_TILE);   // 64 x 4 = 256 CTAs
    for (int t = 0; t < T; t++) {
        lstm_step_kernel<<<grid, N_THREADS, SMEM_TOTAL>>>(bg, bi, bfv, bo, t);
    }
    proj_softmax_kernel<<<1, 256>>>(Wph, bp, out);
}

// round 15
// speedup vs baseline: 1.2619x; 1.2619x over previous
#include <cuda_runtime.h>
#include <cuda_fp16.h>
#include <math.h>
#include <stdint.h>

#define H 1024
#define B 256
#define T 256
#define C 10

#define M_TILE 64
#define N_TILE 64
#define KC 64
#define NCHUNK 16
#define N_THREADS 256
#define NSTAGE 4

#define ROW_BYTES 144
#define A_PLANE_BYTES (M_TILE * ROW_BYTES)      // 9216
#define B_PLANE_BYTES (N_TILE * ROW_BYTES)      // 9216
#define OFF_AH 0
#define OFF_AL A_PLANE_BYTES
#define OFF_B  (2 * A_PLANE_BYTES)
#define STAGE_BYTES (2 * A_PLANE_BYTES + B_PLANE_BYTES)       // 27648
#define SMEM_TOTAL (NSTAGE * STAGE_BYTES)                     // 110592 -> 2 CTA/SM
#define EP_STRIDE 65

// ---- persistent device state (no allocation) ----
__device__ __half  g_pw[2][4096][1024];   // packed W planes [hi/lo][m][k], fp16
__device__ float   g_pwx[4096];           // packed x-weights (same row perm)
__device__ float   g_xT[T * B];           // x transposed [t][b]
__device__ __half  g_hbf[2][B][H];        // [pingpong][b][i], single fp16 plane
__device__ float   g_c[B * H];            // cell state [b][i]
__device__ float   g_h32[B * H];          // fp32 h_T for projection [b][i]

// ---------------- helpers ----------------
__device__ __forceinline__ uint32_t smem_u32(const void* p) {
    uint32_t a;
    asm("{ .reg .u64 t; cvta.to.shared.u64 t, %1; cvt.u32.u64 %0, t; }" : "=r"(a) : "l"(p));
    return a;
}
#define CP_ASYNC16(dst, src) asm volatile("cp.async.cg.shared.global [%0], [%1], 16;" :: "r"(dst), "l"(src) : "memory")
#define CP_COMMIT() asm volatile("cp.async.commit_group;" ::: "memory")
#define CP_WAIT(n)  asm volatile("cp.async.wait_group %0;" :: "n"(n) : "memory")

__device__ __forceinline__ void ldsm_x4(uint32_t* r, uint32_t addr) {
    asm volatile("ldmatrix.sync.aligned.m8n8.x4.shared.b16 {%0,%1,%2,%3}, [%4];"
        : "=r"(r[0]), "=r"(r[1]), "=r"(r[2]), "=r"(r[3]) : "r"(addr));
}
__device__ __forceinline__ void mma_f16(float* d, const uint32_t* a,
                                        uint32_t b0, uint32_t b1) {
    asm volatile("mma.sync.aligned.m16n8k16.row.col.f32.f16.f16.f32 "
        "{%0,%1,%2,%3}, {%4,%5,%6,%7}, {%8,%9}, {%0,%1,%2,%3};"
        : "+f"(d[0]), "+f"(d[1]), "+f"(d[2]), "+f"(d[3])
        : "r"(a[0]), "r"(a[1]), "r"(a[2]), "r"(a[3]), "r"(b0), "r"(b1));
}
__device__ __forceinline__ float sigm(float v) { return 1.0f / (1.0f + __expf(-v)); }
__device__ __forceinline__ float tanh_fast(float v) { return 2.0f * sigm(2.0f * v) - 1.0f; }

// ---------------- pack / init ----------------
// Row permutation: m = ((i>>4) << 6) | (gate << 4) | (i & 15)
__global__ void pack_w_kernel(const float* __restrict__ Wgh, const float* __restrict__ Wih,
                              const float* __restrict__ Wfh, const float* __restrict__ Woh) {
    int idx = blockIdx.x * 256 + threadIdx.x;           // 4M
    int gate = idx >> 20;
    int rem = idx & 0xFFFFF;
    int i = rem >> 10;
    int k = rem & 1023;
    const float* W = (gate == 0) ? Wgh : (gate == 1) ? Wih : (gate == 2) ? Wfh : Woh;
    float w = W[i * H + k];
    __half hi = __float2half_rn(w);
    float lo = w - __half2float(hi);
    int m = ((i >> 4) << 6) + (gate << 4) + (i & 15);
    g_pw[0][m][k] = hi;
    g_pw[1][m][k] = __float2half_rn(lo);
}

__global__ void pack_wx_kernel(const float* __restrict__ Wgx, const float* __restrict__ Wix,
                               const float* __restrict__ Wfx, const float* __restrict__ Wox,
                               const float* __restrict__ x) {
    int idx = blockIdx.x * 256 + threadIdx.x;
    if (idx < 4096) {
        int gate = idx >> 10;
        int i = idx & 1023;
        const float* W = (gate == 0) ? Wgx : (gate == 1) ? Wix : (gate == 2) ? Wfx : Wox;
        int m = ((i >> 4) << 6) + (gate << 4) + (i & 15);
        g_pwx[m] = W[i];
    }
    if (idx < T * B) {
        int tt = idx >> 8;
        int bb = idx & 255;
        g_xT[tt * B + bb] = x[bb * T + tt];
    }
}

__global__ void lstm_init_kernel() {
    int idx = blockIdx.x * 256 + threadIdx.x;           // 524288
    if (idx < 262144) {
        ((uint32_t*)&g_hbf[0][0][0])[idx] = 0;          // zero both pingpong planes (1MB)
    } else {
        g_c[idx - 262144] = 0.0f;
    }
}

// ---------------- one timestep ----------------
// grid (64, 4): mt = 64-row block of packed W (4 gates x 16 h-rows), nt = 64-batch block.
// 8 warps, warp tile 32m x 16n. 2-term fp16 split: W = Wh + Wl, h single fp16.
__global__ void __launch_bounds__(N_THREADS, 2) lstm_step_kernel(
    const float* __restrict__ bg, const float* __restrict__ bi,
    const float* __restrict__ bf, const float* __restrict__ bo,
    int t)
{
    extern __shared__ char smem[];
    const uint32_t sb = smem_u32(smem);
    const int tid = threadIdx.x;
    const int lane = tid & 31;
    const int wid = tid >> 5;
    const int warp_m = wid & 1;          // 2 m-warps x 32 rows
    const int warp_n = wid >> 1;         // 4 n-warps x 16 cols
    const int mt = blockIdx.x;
    const int nt = blockIdx.y;
    const int pp = t & 1;
    const int ppo = pp ^ 1;

    const __half* srcAh = &g_pw[0][mt * M_TILE][0];
    const __half* srcAl = &g_pw[1][mt * M_TILE][0];

    // per-thread cp.async decode: A: 4 x 16B chunks/thread, B: 2 x 16B chunks/thread
    const __half* aSrc[4];
    uint32_t aDst[4];
    const __half* bSrc[2];
    uint32_t bDst[2];
#pragma unroll
    for (int it = 0; it < 4; it++) {
        int i = tid + it * 256;          // [0, 1024)
        int c8 = i & 7, row = (i >> 3) & 63, pl = i >> 9;
        aSrc[it] = (pl ? srcAl : srcAh) + row * H + c8 * 8;
        aDst[it] = (pl ? OFF_AL : OFF_AH) + row * ROW_BYTES + c8 * 16;
    }
#pragma unroll
    for (int it = 0; it < 2; it++) {
        int i = tid + it * 256;          // [0, 512)
        int c8 = i & 7, row = (i >> 3) & 63;
        bSrc[it] = &g_hbf[pp][nt * N_TILE + row][0] + c8 * 8;
        bDst[it] = OFF_B + row * ROW_BYTES + c8 * 16;
    }

    const uint32_t lm_a = (uint32_t)((warp_m * 32 + (lane & 15)) * ROW_BYTES + (lane >> 4) * 16);
    const uint32_t lm_b = (uint32_t)((warp_n * 16 + (lane & 15)) * ROW_BYTES + (lane >> 4) * 16);

    float d[2][2][4];
#pragma unroll
    for (int a = 0; a < 2; a++)
#pragma unroll
        for (int b2 = 0; b2 < 2; b2++)
#pragma unroll
            for (int e = 0; e < 4; e++)
                d[a][b2][e] = 0.0f;

    // ---- prefetch chunks 0, 1, 2 ----
#pragma unroll
    for (int cc = 0; cc < 3; cc++) {
        const uint32_t stg = sb + cc * STAGE_BYTES;
        const int k0 = cc * KC;
#pragma unroll
        for (int it = 0; it < 4; it++)
            CP_ASYNC16(stg + aDst[it], aSrc[it] + k0);
#pragma unroll
        for (int it = 0; it < 2; it++)
            CP_ASYNC16(stg + bDst[it], bSrc[it] + k0);
        CP_COMMIT();
    }

    // ---- main chunk loop: 1 sync per chunk, 4-stage pipeline (3 in flight) ----
    for (int c = 0; c < NCHUNK; c++) {
        if (c < NCHUNK - 2)      CP_WAIT(2);
        else if (c == NCHUNK - 2) CP_WAIT(1);
        else                      CP_WAIT(0);
        __syncthreads();

        if (c + 3 < NCHUNK) {    // refill stage (c+3)%4 (its prior chunk c-1 was consumed)
            const uint32_t stg = sb + ((c + 3) & 3) * STAGE_BYTES;
            const int k0 = (c + 3) * KC;
#pragma unroll
            for (int it = 0; it < 4; it++)
                CP_ASYNC16(stg + aDst[it], aSrc[it] + k0);
#pragma unroll
            for (int it = 0; it < 2; it++)
                CP_ASYNC16(stg + bDst[it], bSrc[it] + k0);
            CP_COMMIT();
        }

        const uint32_t stg = sb + (c & 3) * STAGE_BYTES;
        const uint32_t aBaseH = stg + OFF_AH + lm_a;
        const uint32_t aBaseL = stg + OFF_AL + lm_a;
        const uint32_t bBase  = stg + OFF_B  + lm_b;

#pragma unroll
        for (int k16 = 0; k16 < 4; k16++) {
            const uint32_t koff = (uint32_t)(k16 * 32);
            uint32_t af[2][2][4];   // [plane][m2]
            uint32_t bfr[4];
            ldsm_x4(af[0][0], aBaseH + koff);
            ldsm_x4(af[0][1], aBaseH + koff + 16 * ROW_BYTES);
            ldsm_x4(af[1][0], aBaseL + koff);
            ldsm_x4(af[1][1], aBaseL + koff + 16 * ROW_BYTES);
            ldsm_x4(bfr, bBase + koff);
#pragma unroll
            for (int pa = 0; pa < 2; pa++) {
#pragma unroll
                for (int m2 = 0; m2 < 2; m2++) {
                    mma_f16(d[m2][0], af[pa][m2], bfr[0], bfr[2]);
                    mma_f16(d[m2][1], af[pa][m2], bfr[1], bfr[3]);
                }
            }
        }
    }
    __syncthreads();   // all reads of stage smem done before ep overwrite

    // ---- accumulators -> smem exchange [64][EP_STRIDE] ----
    float* ep = (float*)smem;
#pragma unroll
    for (int m2 = 0; m2 < 2; m2++) {
        const int mrow = warp_m * 32 + m2 * 16 + (lane >> 2);
#pragma unroll
        for (int n8 = 0; n8 < 2; n8++) {
            const int ncol = warp_n * 16 + n8 * 8 + (lane & 3) * 2;
            ep[mrow * EP_STRIDE + ncol]           = d[m2][n8][0];
            ep[mrow * EP_STRIDE + ncol + 1]       = d[m2][n8][1];
            ep[(mrow + 8) * EP_STRIDE + ncol]     = d[m2][n8][2];
            ep[(mrow + 8) * EP_STRIDE + ncol + 1] = d[m2][n8][3];
        }
    }
    __syncthreads();

    // ---- pointwise LSTM update ----
    const int il = tid & 15;
    const int bq = tid >> 4;
    const int ig = mt * 16 + il;
    const float wxg = g_pwx[mt * 64 + 0 * 16 + il];
    const float wxi = g_pwx[mt * 64 + 1 * 16 + il];
    const float wxf = g_pwx[mt * 64 + 2 * 16 + il];
    const float wxo = g_pwx[mt * 64 + 3 * 16 + il];
#pragma unroll
    for (int jj = 0; jj < 4; jj++) {
        const int bl = bq + 16 * jj;
        const int bglob = nt * N_TILE + bl;
        const float xv = g_xT[t * B + bglob];
        const float pg = ep[(0 * 16 + il) * EP_STRIDE + bl] + wxg * xv + bg[bglob];
        const float pi = ep[(1 * 16 + il) * EP_STRIDE + bl] + wxi * xv + bi[bglob];
        const float pf = ep[(2 * 16 + il) * EP_STRIDE + bl] + wxf * xv + bf[bglob];
        const float po = ep[(3 * 16 + il) * EP_STRIDE + bl] + wxo * xv + bo[bglob];

        const float gg = tanh_fast(pg);
        const float ii = sigm(pi);
        const float ff = sigm(pf);
        const float oo = sigm(po);

        const int idx = bglob * H + ig;
        const float cn = gg * ii + g_c[idx] * ff;
        g_c[idx] = cn;
        const float hn = tanh_fast(cn) * oo;
        g_hbf[ppo][bglob][ig] = __float2half_rn(hn);
        if (t == T - 1) g_h32[idx] = hn;
    }
}

// ---------------- projection + softmax ----------------
__global__ void __launch_bounds__(256) proj_softmax_kernel(
    const float* __restrict__ Wph, const float* __restrict__ bp,
    float* __restrict__ out)
{
    const float* __restrict__ hT = g_h32;   // [b][i]
    const int b = threadIdx.x;

    float p[C];
#pragma unroll
    for (int c = 0; c < C; c++) p[c] = 0.0f;
    for (int k = 0; k < H; k++) {
        float hv = hT[b * H + k];
#pragma unroll
        for (int c = 0; c < C; c++)
            p[c] = fmaf(Wph[c * H + k], hv, p[c]);
    }
    float bpb = bp[b];
#pragma unroll
    for (int c = 0; c < C; c++) p[c] += bpb;

    __shared__ float red[256];
    for (int c = 0; c < C; c++) {
        red[b] = p[c];
        __syncthreads();
        for (int s = 128; s > 0; s >>= 1) {
            if (b < s) red[b] = fmaxf(red[b], red[b + s]);
            __syncthreads();
        }
        float m = red[0];
        __syncthreads();
        float e = expf(p[c] - m);
        red[b] = e;
        __syncthreads();
        for (int s = 128; s > 0; s >>= 1) {
            if (b < s) red[b] += red[b + s];
            __syncthreads();
        }
        float ssum = red[0];
        __syncthreads();
        out[b * C + c] = e / ssum;
    }
}

extern "C" void kernel_launch(void* const* d_in, const int* in_sizes, int n_in,
                              void* d_out, int out_size) {
    const float* x   = (const float*)d_in[0];
    const float* Wgx = (const float*)d_in[1];
    const float* Wgh = (const float*)d_in[2];
    const float* Wix = (const float*)d_in[3];
    const float* Wih = (const float*)d_in[4];
    const float* Wfx = (const float*)d_in[5];
    const float* Wfh = (const float*)d_in[6];
    const float* Wox = (const float*)d_in[7];
    const float* Woh = (const float*)d_in[8];
    const float* Wph = (const float*)d_in[9];
    const float* bg  = (const float*)d_in[10];
    const float* bi  = (const float*)d_in[11];
    const float* bfv = (const float*)d_in[12];
    const float* bo  = (const float*)d_in[13];
    const float* bp  = (const float*)d_in[14];
    float* out = (float*)d_out;

    cudaFuncSetAttribute(lstm_step_kernel,
                         cudaFuncAttributeMaxDynamicSharedMemorySize, SMEM_TOTAL);

    pack_w_kernel<<<4 * 1024 * 1024 / 256, 256>>>(Wgh, Wih, Wfh, Woh);
    pack_wx_kernel<<<(T * B + 255) / 256, 256>>>(Wgx, Wix, Wfx, Wox, x);
    lstm_init_kernel<<<524288 / 256, 256>>>();

    dim3 grid(4096 / M_TILE, B / N_TILE);   // 64 x 4 = 256 CTAs
    for (int t = 0; t < T; t++) {
        lstm_step_kernel<<<grid, N_THREADS, SMEM_TOTAL>>>(bg, bi, bfv, bo, t);
    }
    proj_softmax_kernel<<<1, 256>>>(Wph, bp, out);
}

// round 16
// speedup vs baseline: 1.2885x; 1.0211x over previous
#include <cuda_runtime.h>
#include <cuda_fp16.h>
#include <math.h>
#include <stdint.h>

#define H 1024
#define B 256
#define T 256
#define C 10

#define M_TILE 64
#define N_TILE 128
#define KC 64
#define NCHUNK 16
#define N_THREADS 256
#define NSTAGE 3

#define ROW_BYTES 144
#define A_PLANE_BYTES (M_TILE * ROW_BYTES)      // 9216
#define B_PLANE_BYTES (N_TILE * ROW_BYTES)      // 18432
#define OFF_AH 0
#define OFF_AL A_PLANE_BYTES
#define OFF_B  (2 * A_PLANE_BYTES)
#define STAGE_BYTES (2 * A_PLANE_BYTES + B_PLANE_BYTES)       // 36864
#define SMEM_TOTAL (NSTAGE * STAGE_BYTES)                     // 110592
#define EP_STRIDE 129

// ---- persistent device state (no allocation) ----
__device__ __half  g_pw[2][4096][1024];   // packed W planes [hi/lo][m][k], fp16
__device__ float   g_pwx[4096];           // packed x-weights (same row perm)
__device__ float   g_xT[T * B];           // x transposed [t][b]
__device__ __half  g_hbf[2][B][H];        // [pingpong][b][i], single fp16 plane
__device__ float   g_c[B * H];            // cell state [b][i]
__device__ float   g_h32[B * H];          // fp32 h_T for projection [b][i]

// ---------------- helpers ----------------
__device__ __forceinline__ uint32_t smem_u32(const void* p) {
    uint32_t a;
    asm("{ .reg .u64 t; cvta.to.shared.u64 t, %1; cvt.u32.u64 %0, t; }" : "=r"(a) : "l"(p));
    return a;
}
#define CP_ASYNC16(dst, src) asm volatile("cp.async.cg.shared.global [%0], [%1], 16;" :: "r"(dst), "l"(src) : "memory")
#define CP_COMMIT() asm volatile("cp.async.commit_group;" ::: "memory")
#define CP_WAIT(n)  asm volatile("cp.async.wait_group %0;" :: "n"(n) : "memory")

__device__ __forceinline__ void ldsm_x4(uint32_t* r, uint32_t addr) {
    asm volatile("ldmatrix.sync.aligned.m8n8.x4.shared.b16 {%0,%1,%2,%3}, [%4];"
        : "=r"(r[0]), "=r"(r[1]), "=r"(r[2]), "=r"(r[3]) : "r"(addr));
}
__device__ __forceinline__ void mma_f16(float* d, const uint32_t* a,
                                        uint32_t b0, uint32_t b1) {
    asm volatile("mma.sync.aligned.m16n8k16.row.col.f32.f16.f16.f32 "
        "{%0,%1,%2,%3}, {%4,%5,%6,%7}, {%8,%9}, {%0,%1,%2,%3};"
        : "+f"(d[0]), "+f"(d[1]), "+f"(d[2]), "+f"(d[3])
        : "r"(a[0]), "r"(a[1]), "r"(a[2]), "r"(a[3]), "r"(b0), "r"(b1));
}
__device__ __forceinline__ float sigm(float v) { return 1.0f / (1.0f + __expf(-v)); }
__device__ __forceinline__ float tanh_fast(float v) { return 2.0f * sigm(2.0f * v) - 1.0f; }

// ---------------- pack / init ----------------
// Row permutation: m = ((i>>4) << 6) | (gate << 4) | (i & 15)
__global__ void pack_w_kernel(const float* __restrict__ Wgh, const float* __restrict__ Wih,
                              const float* __restrict__ Wfh, const float* __restrict__ Woh) {
    int idx = blockIdx.x * 256 + threadIdx.x;           // 4M
    int gate = idx >> 20;
    int rem = idx & 0xFFFFF;
    int i = rem >> 10;
    int k = rem & 1023;
    const float* W = (gate == 0) ? Wgh : (gate == 1) ? Wih : (gate == 2) ? Wfh : Woh;
    float w = W[i * H + k];
    __half hi = __float2half_rn(w);
    float lo = w - __half2float(hi);
    int m = ((i >> 4) << 6) + (gate << 4) + (i & 15);
    g_pw[0][m][k] = hi;
    g_pw[1][m][k] = __float2half_rn(lo);
}

__global__ void pack_wx_kernel(const float* __restrict__ Wgx, const float* __restrict__ Wix,
                               const float* __restrict__ Wfx, const float* __restrict__ Wox,
                               const float* __restrict__ x) {
    int idx = blockIdx.x * 256 + threadIdx.x;
    if (idx < 4096) {
        int gate = idx >> 10;
        int i = idx & 1023;
        const float* W = (gate == 0) ? Wgx : (gate == 1) ? Wix : (gate == 2) ? Wfx : Wox;
        int m = ((i >> 4) << 6) + (gate << 4) + (i & 15);
        g_pwx[m] = W[i];
    }
    if (idx < T * B) {
        int tt = idx >> 8;
        int bb = idx & 255;
        g_xT[tt * B + bb] = x[bb * T + tt];
    }
}

__global__ void lstm_init_kernel() {
    int idx = blockIdx.x * 256 + threadIdx.x;           // 524288
    if (idx < 262144) {
        ((uint32_t*)&g_hbf[0][0][0])[idx] = 0;          // zero both pingpong planes (1MB)
    } else {
        g_c[idx - 262144] = 0.0f;
    }
}

// ---------------- one timestep ----------------
// grid (64, 2) = 128 CTAs -> 1 CTA/SM. CTA tile 64m x 128n.
// 8 warps, warp tile 32x32 (2m x 4n). 2-term fp16 split: W = Wh + Wl, h single fp16.
__global__ void __launch_bounds__(N_THREADS) lstm_step_kernel(
    const float* __restrict__ bg, const float* __restrict__ bi,
    const float* __restrict__ bf, const float* __restrict__ bo,
    int t)
{
    extern __shared__ char smem[];
    const uint32_t sb = smem_u32(smem);
    const int tid = threadIdx.x;
    const int lane = tid & 31;
    const int wid = tid >> 5;
    const int warp_m = wid & 1;          // 2 m-warps x 32 rows
    const int warp_n = wid >> 1;         // 4 n-warps x 32 cols
    const int mt = blockIdx.x;           // 0..63
    const int nt = blockIdx.y;           // 0..1
    const int pp = t & 1;
    const int ppo = pp ^ 1;

    const __half* srcAh = &g_pw[0][mt * M_TILE][0];
    const __half* srcAl = &g_pw[1][mt * M_TILE][0];

    // per-thread cp.async decode: A: 4 x 16B chunks/thread, B: 4 x 16B chunks/thread
    const __half* aSrc[4];
    uint32_t aDst[4];
    const __half* bSrc[4];
    uint32_t bDst[4];
#pragma unroll
    for (int it = 0; it < 4; it++) {
        int i = tid + it * 256;          // [0, 1024)
        int c8 = i & 7, arow = (i >> 3) & 63, pl = i >> 9;
        aSrc[it] = (pl ? srcAl : srcAh) + arow * H + c8 * 8;
        aDst[it] = (pl ? OFF_AL : OFF_AH) + arow * ROW_BYTES + c8 * 16;
        int brow = (i >> 3) & 127;       // [0, 128)
        bSrc[it] = &g_hbf[pp][nt * N_TILE + brow][0] + c8 * 8;
        bDst[it] = OFF_B + brow * ROW_BYTES + c8 * 16;
    }

    const uint32_t lm_a = (uint32_t)((warp_m * 32 + (lane & 15)) * ROW_BYTES + (lane >> 4) * 16);
    const uint32_t lm_b = (uint32_t)((warp_n * 32 + (lane & 15)) * ROW_BYTES + (lane >> 4) * 16);

    float d[2][4][4];    // [m2][n8] warp 32x32 accumulators
#pragma unroll
    for (int a = 0; a < 2; a++)
#pragma unroll
        for (int b2 = 0; b2 < 4; b2++)
#pragma unroll
            for (int e = 0; e < 4; e++)
                d[a][b2][e] = 0.0f;

    // ---- prefetch chunks 0, 1 ----
#pragma unroll
    for (int cc = 0; cc < 2; cc++) {
        const uint32_t stg = sb + cc * STAGE_BYTES;
        const int k0 = cc * KC;
#pragma unroll
        for (int it = 0; it < 4; it++) {
            CP_ASYNC16(stg + aDst[it], aSrc[it] + k0);
            CP_ASYNC16(stg + bDst[it], bSrc[it] + k0);
        }
        CP_COMMIT();
    }

    // ---- main chunk loop: 1 sync per chunk, 3-stage pipeline ----
    for (int c = 0; c < NCHUNK; c++) {
        if (c < NCHUNK - 1) CP_WAIT(1);
        else                CP_WAIT(0);
        __syncthreads();

        if (c + 2 < NCHUNK) {
            const uint32_t stg = sb + ((c + 2) % 3) * STAGE_BYTES;
            const int k0 = (c + 2) * KC;
#pragma unroll
            for (int it = 0; it < 4; it++) {
                CP_ASYNC16(stg + aDst[it], aSrc[it] + k0);
                CP_ASYNC16(stg + bDst[it], bSrc[it] + k0);
            }
            CP_COMMIT();
        }

        const uint32_t stg = sb + (c % 3) * STAGE_BYTES;
        const uint32_t aBaseH = stg + OFF_AH + lm_a;
        const uint32_t aBaseL = stg + OFF_AL + lm_a;
        const uint32_t bBase  = stg + OFF_B  + lm_b;

#pragma unroll
        for (int k16 = 0; k16 < 4; k16++) {
            const uint32_t koff = (uint32_t)(k16 * 32);
            uint32_t af[2][2][4];   // [plane][m2]
            uint32_t bfr[2][4];     // [n16-half]
            ldsm_x4(af[0][0], aBaseH + koff);
            ldsm_x4(af[0][1], aBaseH + koff + 16 * ROW_BYTES);
            ldsm_x4(af[1][0], aBaseL + koff);
            ldsm_x4(af[1][1], aBaseL + koff + 16 * ROW_BYTES);
            ldsm_x4(bfr[0], bBase + koff);
            ldsm_x4(bfr[1], bBase + koff + 16 * ROW_BYTES);
#pragma unroll
            for (int pa = 0; pa < 2; pa++) {
#pragma unroll
                for (int m2 = 0; m2 < 2; m2++) {
                    mma_f16(d[m2][0], af[pa][m2], bfr[0][0], bfr[0][2]);
                    mma_f16(d[m2][1], af[pa][m2], bfr[0][1], bfr[0][3]);
                    mma_f16(d[m2][2], af[pa][m2], bfr[1][0], bfr[1][2]);
                    mma_f16(d[m2][3], af[pa][m2], bfr[1][1], bfr[1][3]);
                }
            }
        }
    }
    __syncthreads();   // all reads of stage smem done before ep overwrite

    // ---- accumulators -> smem exchange [64][EP_STRIDE] ----
    float* ep = (float*)smem;
#pragma unroll
    for (int m2 = 0; m2 < 2; m2++) {
        const int mrow = warp_m * 32 + m2 * 16 + (lane >> 2);
#pragma unroll
        for (int n8 = 0; n8 < 4; n8++) {
            const int ncol = warp_n * 32 + n8 * 8 + (lane & 3) * 2;
            ep[mrow * EP_STRIDE + ncol]           = d[m2][n8][0];
            ep[mrow * EP_STRIDE + ncol + 1]       = d[m2][n8][1];
            ep[(mrow + 8) * EP_STRIDE + ncol]     = d[m2][n8][2];
            ep[(mrow + 8) * EP_STRIDE + ncol + 1] = d[m2][n8][3];
        }
    }
    __syncthreads();

    // ---- pointwise LSTM update (256 threads: 16 i-rows x 16 b-col groups) ----
    const int il = tid & 15;
    const int bq = tid >> 4;             // 0..15
    const int ig = mt * 16 + il;
    const float wxg = g_pwx[mt * 64 + 0 * 16 + il];
    const float wxi = g_pwx[mt * 64 + 1 * 16 + il];
    const float wxf = g_pwx[mt * 64 + 2 * 16 + il];
    const float wxo = g_pwx[mt * 64 + 3 * 16 + il];
#pragma unroll
    for (int jj = 0; jj < 8; jj++) {
        const int bl = bq + 16 * jj;
        const int bglob = nt * N_TILE + bl;
        const float xv = g_xT[t * B + bglob];
        const float pg = ep[(0 * 16 + il) * EP_STRIDE + bl] + wxg * xv + bg[bglob];
        const float pi = ep[(1 * 16 + il) * EP_STRIDE + bl] + wxi * xv + bi[bglob];
        const float pf = ep[(2 * 16 + il) * EP_STRIDE + bl] + wxf * xv + bf[bglob];
        const float po = ep[(3 * 16 + il) * EP_STRIDE + bl] + wxo * xv + bo[bglob];

        const float gg = tanh_fast(pg);
        const float ii = sigm(pi);
        const float ff = sigm(pf);
        const float oo = sigm(po);

        const int idx = bglob * H + ig;
        const float cn = gg * ii + g_c[idx] * ff;
        g_c[idx] = cn;
        const float hn = tanh_fast(cn) * oo;
        g_hbf[ppo][bglob][ig] = __float2half_rn(hn);
        if (t == T - 1) g_h32[idx] = hn;
    }
}

// ---------------- projection + softmax ----------------
__global__ void __launch_bounds__(256) proj_softmax_kernel(
    const float* __restrict__ Wph, const float* __restrict__ bp,
    float* __restrict__ out)
{
    const float* __restrict__ hT = g_h32;   // [b][i]
    const int b = threadIdx.x;

    float p[C];
#pragma unroll
    for (int c = 0; c < C; c++) p[c] = 0.0f;
    for (int k = 0; k < H; k++) {
        float hv = hT[b * H + k];
#pragma unroll
        for (int c = 0; c < C; c++)
            p[c] = fmaf(Wph[c * H + k], hv, p[c]);
    }
    float bpb = bp[b];
#pragma unroll
    for (int c = 0; c < C; c++) p[c] += bpb;

    __shared__ float red[256];
    for (int c = 0; c < C; c++) {
        red[b] = p[c];
        __syncthreads();
        for (int s = 128; s > 0; s >>= 1) {
            if (b < s) red[b] = fmaxf(red[b], red[b + s]);
            __syncthreads();
        }
        float m = red[0];
        __syncthreads();
        float e = expf(p[c] - m);
        red[b] = e;
        __syncthreads();
        for (int s = 128; s > 0; s >>= 1) {
            if (b < s) red[b] += red[b + s];
            __syncthreads();
        }
        float ssum = red[0];
        __syncthreads();
        out[b * C + c] = e / ssum;
    }
}

extern "C" void kernel_launch(void* const* d_in, const int* in_sizes, int n_in,
                              void* d_out, int out_size) {
    const float* x   = (const float*)d_in[0];
    const float* Wgx = (const float*)d_in[1];
    const float* Wgh = (const float*)d_in[2];
    const float* Wix = (const float*)d_in[3];
    const float* Wih = (const float*)d_in[4];
    const float* Wfx = (const float*)d_in[5];
    const float* Wfh = (const float*)d_in[6];
    const float* Wox = (const float*)d_in[7];
    const float* Woh = (const float*)d_in[8];
    const float* Wph = (const float*)d_in[9];
    const float* bg  = (const float*)d_in[10];
    const float* bi  = (const float*)d_in[11];
    const float* bfv = (const float*)d_in[12];
    const float* bo  = (const float*)d_in[13];
    const float* bp  = (const float*)d_in[14];
    float* out = (float*)d_out;

    cudaFuncSetAttribute(lstm_step_kernel,
                         cudaFuncAttributeMaxDynamicSharedMemorySize, SMEM_TOTAL);

    pack_w_kernel<<<4 * 1024 * 1024 / 256, 256>>>(Wgh, Wih, Wfh, Woh);
    pack_wx_kernel<<<(T * B + 255) / 256, 256>>>(Wgx, Wix, Wfx, Wox, x);
    lstm_init_kernel<<<524288 / 256, 256>>>();

    dim3 grid(4096 / M_TILE, B / N_TILE);   // 64 x 2 = 128 CTAs, 1/SM
    for (int t = 0; t < T; t++) {
        lstm_step_kernel<<<grid, N_THREADS, SMEM_TOTAL>>>(bg, bi, bfv, bo, t);
    }
    proj_softmax_kernel<<<1, 256>>>(Wph, bp, out);
}

// round 17
// speedup vs baseline: 1.4889x; 1.1555x over previous
#include <cuda_runtime.h>
#include <cuda_fp16.h>
#include <math.h>
#include <stdint.h>

#define H 1024
#define B 256
#define T 256
#define C 10

#define M_TILE 64
#define N_TILE 128
#define KC 64
#define NCHUNK 16
#define N_THREADS 512
#define NSTAGE 4

#define ROW_BYTES 144
#define A_PLANE_BYTES (M_TILE * ROW_BYTES)      // 9216
#define B_PLANE_BYTES (N_TILE * ROW_BYTES)      // 18432
#define OFF_AH 0
#define OFF_AL A_PLANE_BYTES
#define OFF_B  (2 * A_PLANE_BYTES)
#define STAGE_BYTES (2 * A_PLANE_BYTES + B_PLANE_BYTES)       // 36864
#define SMEM_TOTAL (NSTAGE * STAGE_BYTES)                     // 147456, 1 CTA/SM
#define EP_STRIDE 129
#define EP_PLANE (64 * EP_STRIDE)               // floats per K-group plane

// ---- persistent device state (no allocation) ----
__device__ __half  g_pw[2][4096][1024];   // packed W planes [hi/lo][m][k], fp16
__device__ float   g_pwx[4096];           // packed x-weights (same row perm)
__device__ float   g_xT[T * B];           // x transposed [t][b]
__device__ __half  g_hbf[2][B][H];        // [pingpong][b][i], single fp16 plane
__device__ float   g_c[B * H];            // cell state [b][i]
__device__ float   g_h32[B * H];          // fp32 h_T for projection [b][i]

// ---------------- helpers ----------------
__device__ __forceinline__ uint32_t smem_u32(const void* p) {
    uint32_t a;
    asm("{ .reg .u64 t; cvta.to.shared.u64 t, %1; cvt.u32.u64 %0, t; }" : "=r"(a) : "l"(p));
    return a;
}
#define CP_ASYNC16(dst, src) asm volatile("cp.async.cg.shared.global [%0], [%1], 16;" :: "r"(dst), "l"(src) : "memory")
#define CP_COMMIT() asm volatile("cp.async.commit_group;" ::: "memory")
#define CP_WAIT(n)  asm volatile("cp.async.wait_group %0;" :: "n"(n) : "memory")

__device__ __forceinline__ void ldsm_x4(uint32_t* r, uint32_t addr) {
    asm volatile("ldmatrix.sync.aligned.m8n8.x4.shared.b16 {%0,%1,%2,%3}, [%4];"
        : "=r"(r[0]), "=r"(r[1]), "=r"(r[2]), "=r"(r[3]) : "r"(addr));
}
__device__ __forceinline__ void mma_f16(float* d, const uint32_t* a,
                                        uint32_t b0, uint32_t b1) {
    asm volatile("mma.sync.aligned.m16n8k16.row.col.f32.f16.f16.f32 "
        "{%0,%1,%2,%3}, {%4,%5,%6,%7}, {%8,%9}, {%0,%1,%2,%3};"
        : "+f"(d[0]), "+f"(d[1]), "+f"(d[2]), "+f"(d[3])
        : "r"(a[0]), "r"(a[1]), "r"(a[2]), "r"(a[3]), "r"(b0), "r"(b1));
}
__device__ __forceinline__ float sigm(float v) { return 1.0f / (1.0f + __expf(-v)); }
__device__ __forceinline__ float tanh_fast(float v) { return 2.0f * sigm(2.0f * v) - 1.0f; }

// ---------------- pack / init ----------------
// Row permutation: m = ((i>>4) << 6) | (gate << 4) | (i & 15)
__global__ void pack_w_kernel(const float* __restrict__ Wgh, const float* __restrict__ Wih,
                              const float* __restrict__ Wfh, const float* __restrict__ Woh) {
    int idx = blockIdx.x * 256 + threadIdx.x;           // 4M
    int gate = idx >> 20;
    int rem = idx & 0xFFFFF;
    int i = rem >> 10;
    int k = rem & 1023;
    const float* W = (gate == 0) ? Wgh : (gate == 1) ? Wih : (gate == 2) ? Wfh : Woh;
    float w = W[i * H + k];
    __half hi = __float2half_rn(w);
    float lo = w - __half2float(hi);
    int m = ((i >> 4) << 6) + (gate << 4) + (i & 15);
    g_pw[0][m][k] = hi;
    g_pw[1][m][k] = __float2half_rn(lo);
}

__global__ void pack_wx_kernel(const float* __restrict__ Wgx, const float* __restrict__ Wix,
                               const float* __restrict__ Wfx, const float* __restrict__ Wox,
                               const float* __restrict__ x) {
    int idx = blockIdx.x * 256 + threadIdx.x;
    if (idx < 4096) {
        int gate = idx >> 10;
        int i = idx & 1023;
        const float* W = (gate == 0) ? Wgx : (gate == 1) ? Wix : (gate == 2) ? Wfx : Wox;
        int m = ((i >> 4) << 6) + (gate << 4) + (i & 15);
        g_pwx[m] = W[i];
    }
    if (idx < T * B) {
        int tt = idx >> 8;
        int bb = idx & 255;
        g_xT[tt * B + bb] = x[bb * T + tt];
    }
}

__global__ void lstm_init_kernel() {
    int idx = blockIdx.x * 256 + threadIdx.x;           // 524288
    if (idx < 262144) {
        ((uint32_t*)&g_hbf[0][0][0])[idx] = 0;          // zero both pingpong planes (1MB)
    } else {
        g_c[idx - 262144] = 0.0f;
    }
}

// ---------------- one timestep ----------------
// grid (64, 2) = 128 CTAs -> 1 CTA/SM. CTA tile 64m x 128n.
// 16 warps: 2 K-groups x (2m x 4n) warps of 32x32 tiles. In-CTA split-K:
// group g handles k16 = 2g, 2g+1 of each chunk; partials summed in epilogue.
__global__ void __launch_bounds__(N_THREADS) lstm_step_kernel(
    const float* __restrict__ bg, const float* __restrict__ bi,
    const float* __restrict__ bf, const float* __restrict__ bo,
    int t)
{
    extern __shared__ char smem[];
    const uint32_t sb = smem_u32(smem);
    const int tid = threadIdx.x;
    const int lane = tid & 31;
    const int wid = tid >> 5;            // 0..15
    const int kgrp = wid >> 3;           // 0..1 : K-split group
    const int w8 = wid & 7;
    const int warp_m = w8 & 1;           // 2 m-warps x 32 rows
    const int warp_n = w8 >> 1;          // 4 n-warps x 32 cols
    const int mt = blockIdx.x;           // 0..63
    const int nt = blockIdx.y;           // 0..1
    const int pp = t & 1;
    const int ppo = pp ^ 1;

    const __half* srcAh = &g_pw[0][mt * M_TILE][0];
    const __half* srcAl = &g_pw[1][mt * M_TILE][0];

    // per-thread cp.async decode: A: 2 x 16B chunks/thread, B: 2 x 16B chunks/thread
    const __half* aSrc[2];
    uint32_t aDst[2];
    const __half* bSrc[2];
    uint32_t bDst[2];
#pragma unroll
    for (int it = 0; it < 2; it++) {
        int i = tid + it * 512;          // [0, 1024)
        int c8 = i & 7, arow = (i >> 3) & 63, pl = i >> 9;
        aSrc[it] = (pl ? srcAl : srcAh) + arow * H + c8 * 8;
        aDst[it] = (pl ? OFF_AL : OFF_AH) + arow * ROW_BYTES + c8 * 16;
        int brow = (i >> 3) & 127;       // [0, 128)
        bSrc[it] = &g_hbf[pp][nt * N_TILE + brow][0] + c8 * 8;
        bDst[it] = OFF_B + brow * ROW_BYTES + c8 * 16;
    }

    const uint32_t lm_a = (uint32_t)((warp_m * 32 + (lane & 15)) * ROW_BYTES + (lane >> 4) * 16);
    const uint32_t lm_b = (uint32_t)((warp_n * 32 + (lane & 15)) * ROW_BYTES + (lane >> 4) * 16);
    const uint32_t kg_off = (uint32_t)(kgrp * 64);      // K-group base byte offset (2 k16 = 64B)

    float d[2][4][4];    // [m2][n8] warp 32x32 accumulators (half-K partials)
#pragma unroll
    for (int a = 0; a < 2; a++)
#pragma unroll
        for (int b2 = 0; b2 < 4; b2++)
#pragma unroll
            for (int e = 0; e < 4; e++)
                d[a][b2][e] = 0.0f;

    // ---- prefetch chunks 0, 1, 2 ----
#pragma unroll
    for (int cc = 0; cc < 3; cc++) {
        const uint32_t stg = sb + cc * STAGE_BYTES;
        const int k0 = cc * KC;
#pragma unroll
        for (int it = 0; it < 2; it++) {
            CP_ASYNC16(stg + aDst[it], aSrc[it] + k0);
            CP_ASYNC16(stg + bDst[it], bSrc[it] + k0);
        }
        CP_COMMIT();
    }

    // ---- main chunk loop: 1 sync per chunk, 4-stage pipeline (3 in flight) ----
    for (int c = 0; c < NCHUNK; c++) {
        if (c < NCHUNK - 2)       CP_WAIT(2);
        else if (c == NCHUNK - 2) CP_WAIT(1);
        else                      CP_WAIT(0);
        __syncthreads();

        if (c + 3 < NCHUNK) {
            const uint32_t stg = sb + ((c + 3) & 3) * STAGE_BYTES;
            const int k0 = (c + 3) * KC;
#pragma unroll
            for (int it = 0; it < 2; it++) {
                CP_ASYNC16(stg + aDst[it], aSrc[it] + k0);
                CP_ASYNC16(stg + bDst[it], bSrc[it] + k0);
            }
            CP_COMMIT();
        }

        const uint32_t stg = sb + (c & 3) * STAGE_BYTES;
        const uint32_t aBaseH = stg + OFF_AH + lm_a + kg_off;
        const uint32_t aBaseL = stg + OFF_AL + lm_a + kg_off;
        const uint32_t bBase  = stg + OFF_B  + lm_b + kg_off;

#pragma unroll
        for (int kk = 0; kk < 2; kk++) {          // this K-group's two k16 slices
            const uint32_t koff = (uint32_t)(kk * 32);
            uint32_t af[2][2][4];   // [plane][m2]
            uint32_t bfr[2][4];     // [n16-half]
            ldsm_x4(af[0][0], aBaseH + koff);
            ldsm_x4(af[0][1], aBaseH + koff + 16 * ROW_BYTES);
            ldsm_x4(af[1][0], aBaseL + koff);
            ldsm_x4(af[1][1], aBaseL + koff + 16 * ROW_BYTES);
            ldsm_x4(bfr[0], bBase + koff);
            ldsm_x4(bfr[1], bBase + koff + 16 * ROW_BYTES);
#pragma unroll
            for (int pa = 0; pa < 2; pa++) {
#pragma unroll
                for (int m2 = 0; m2 < 2; m2++) {
                    mma_f16(d[m2][0], af[pa][m2], bfr[0][0], bfr[0][2]);
                    mma_f16(d[m2][1], af[pa][m2], bfr[0][1], bfr[0][3]);
                    mma_f16(d[m2][2], af[pa][m2], bfr[1][0], bfr[1][2]);
                    mma_f16(d[m2][3], af[pa][m2], bfr[1][1], bfr[1][3]);
                }
            }
        }
    }
    __syncthreads();   // all reads of stage smem done before ep overwrite

    // ---- accumulators -> smem exchange, one plane per K-group ----
    float* ep = (float*)smem + kgrp * EP_PLANE;
#pragma unroll
    for (int m2 = 0; m2 < 2; m2++) {
        const int mrow = warp_m * 32 + m2 * 16 + (lane >> 2);
#pragma unroll
        for (int n8 = 0; n8 < 4; n8++) {
            const int ncol = warp_n * 32 + n8 * 8 + (lane & 3) * 2;
            ep[mrow * EP_STRIDE + ncol]           = d[m2][n8][0];
            ep[mrow * EP_STRIDE + ncol + 1]       = d[m2][n8][1];
            ep[(mrow + 8) * EP_STRIDE + ncol]     = d[m2][n8][2];
            ep[(mrow + 8) * EP_STRIDE + ncol + 1] = d[m2][n8][3];
        }
    }
    __syncthreads();

    // ---- pointwise LSTM update (512 threads: 16 i-rows x 32 b-col groups) ----
    float* ep0 = (float*)smem;
    float* ep1 = (float*)smem + EP_PLANE;
    const int il = tid & 15;
    const int bq = tid >> 4;             // 0..31
    const int ig = mt * 16 + il;
    const float wxg = g_pwx[mt * 64 + 0 * 16 + il];
    const float wxi = g_pwx[mt * 64 + 1 * 16 + il];
    const float wxf = g_pwx[mt * 64 + 2 * 16 + il];
    const float wxo = g_pwx[mt * 64 + 3 * 16 + il];
#pragma unroll
    for (int jj = 0; jj < 4; jj++) {
        const int bl = bq + 32 * jj;
        const int bglob = nt * N_TILE + bl;
        const float xv = g_xT[t * B + bglob];
        const int r0 = (0 * 16 + il) * EP_STRIDE + bl;
        const int r1 = (1 * 16 + il) * EP_STRIDE + bl;
        const int r2 = (2 * 16 + il) * EP_STRIDE + bl;
        const int r3 = (3 * 16 + il) * EP_STRIDE + bl;
        const float pg = ep0[r0] + ep1[r0] + wxg * xv + bg[bglob];
        const float pi = ep0[r1] + ep1[r1] + wxi * xv + bi[bglob];
        const float pf = ep0[r2] + ep1[r2] + wxf * xv + bf[bglob];
        const float po = ep0[r3] + ep1[r3] + wxo * xv + bo[bglob];

        const float gg = tanh_fast(pg);
        const float ii = sigm(pi);
        const float ff = sigm(pf);
        const float oo = sigm(po);

        const int idx = bglob * H + ig;
        const float cn = gg * ii + g_c[idx] * ff;
        g_c[idx] = cn;
        const float hn = tanh_fast(cn) * oo;
        g_hbf[ppo][bglob][ig] = __float2half_rn(hn);
        if (t == T - 1) g_h32[idx] = hn;
    }
}

// ---------------- projection + softmax ----------------
__global__ void __launch_bounds__(256) proj_softmax_kernel(
    const float* __restrict__ Wph, const float* __restrict__ bp,
    float* __restrict__ out)
{
    const float* __restrict__ hT = g_h32;   // [b][i]
    const int b = threadIdx.x;

    float p[C];
#pragma unroll
    for (int c = 0; c < C; c++) p[c] = 0.0f;
    for (int k = 0; k < H; k++) {
        float hv = hT[b * H + k];
#pragma unroll
        for (int c = 0; c < C; c++)
            p[c] = fmaf(Wph[c * H + k], hv, p[c]);
    }
    float bpb = bp[b];
#pragma unroll
    for (int c = 0; c < C; c++) p[c] += bpb;

    __shared__ float red[256];
    for (int c = 0; c < C; c++) {
        red[b] = p[c];
        __syncthreads();
        for (int s = 128; s > 0; s >>= 1) {
            if (b < s) red[b] = fmaxf(red[b], red[b + s]);
            __syncthreads();
        }
        float m = red[0];
        __syncthreads();
        float e = expf(p[c] - m);
        red[b] = e;
        __syncthreads();
        for (int s = 128; s > 0; s >>= 1) {
            if (b < s) red[b] += red[b + s];
            __syncthreads();
        }
        float ssum = red[0];
        __syncthreads();
        out[b * C + c] = e / ssum;
    }
}

extern "C" void kernel_launch(void* const* d_in, const int* in_sizes, int n_in,
                              void* d_out, int out_size) {
    const float* x   = (const float*)d_in[0];
    const float* Wgx = (const float*)d_in[1];
    const float* Wgh = (const float*)d_in[2];
    const float* Wix = (const float*)d_in[3];
    const float* Wih = (const float*)d_in[4];
    const float* Wfx = (const float*)d_in[5];
    const float* Wfh = (const float*)d_in[6];
    const float* Wox = (const float*)d_in[7];
    const float* Woh = (const float*)d_in[8];
    const float* Wph = (const float*)d_in[9];
    const float* bg  = (const float*)d_in[10];
    const float* bi  = (const float*)d_in[11];
    const float* bfv = (const float*)d_in[12];
    const float* bo  = (const float*)d_in[13];
    const float* bp  = (const float*)d_in[14];
    float* out = (float*)d_out;

    cudaFuncSetAttribute(lstm_step_kernel,
                         cudaFuncAttributeMaxDynamicSharedMemorySize, SMEM_TOTAL);

    pack_w_kernel<<<4 * 1024 * 1024 / 256, 256>>>(Wgh, Wih, Wfh, Woh);
    pack_wx_kernel<<<(T * B + 255) / 256, 256>>>(Wgx, Wix, Wfx, Wox, x);
    lstm_init_kernel<<<524288 / 256, 256>>>();

    dim3 grid(4096 / M_TILE, B / N_TILE);   // 64 x 2 = 128 CTAs, 1/SM
    for (int t = 0; t < T; t++) {
        lstm_step_kernel<<<grid, N_THREADS, SMEM_TOTAL>>>(bg, bi, bfv, bo, t);
    }
    proj_softmax_kernel<<<1, 256>>>(Wph, bp, out);
}